// round 2
// baseline (speedup 1.0000x reference)
#include <cuda_runtime.h>
#include <cuda_fp16.h>

#define NN 100000
#define NE 1600000

// xw in fp16: [N][25 kernels][32 feats] = 1600B/node = 160 MB scratch
__device__ uint4 g_xwh[(size_t)NN * 100];      // 100 uint4 (1600B) per node
__device__ float g_acc[(size_t)NN * 32];
__device__ float g_xrb[(size_t)NN * 32];
__device__ float g_rdot[NN];
__device__ float g_denom[NN];

typedef unsigned long long u64;

__device__ __forceinline__ u64 pack2(float a, float b) {
    u64 r; asm("mov.b64 %0,{%1,%2};" : "=l"(r) : "f"(a), "f"(b)); return r;
}
__device__ __forceinline__ void unpack2(u64 v, float& a, float& b) {
    asm("mov.b64 {%0,%1},%2;" : "=f"(a), "=f"(b) : "l"(v));
}
// packed fp32x2 FMA — 2x scalar FFMA throughput on sm_103a
__device__ __forceinline__ u64 fma2(u64 a, u64 b, u64 c) {
    u64 d; asm("fma.rn.f32x2 %0,%1,%2,%3;" : "=l"(d) : "l"(a), "l"(b), "l"(c)); return d;
}
// fp32 pair -> packed half2 bits
__device__ __forceinline__ unsigned h2bits(u64 v) {
    float a, b; unpack2(v, a, b);
    unsigned r; asm("cvt.rn.f16x2.f32 %0,%2,%1;" : "=r"(r) : "f"(a), "f"(b));
    return r;   // low half = a, high half = b
}

// ---------------------------------------------------------------------------
// K1: per-node root transform + attention dot + zero-init of accumulators
// ---------------------------------------------------------------------------
__global__ __launch_bounds__(256) void k1_node(
    const float* __restrict__ x, const float* __restrict__ rootW,
    const float* __restrict__ attW, const float* __restrict__ bias)
{
    __shared__ __align__(16) float Rs[1024];
    __shared__ float a1s[32], bsh[32];
    int tid = threadIdx.x;
    ((float4*)Rs)[tid] = ((const float4*)rootW)[tid];
    if (tid < 32) { a1s[tid] = attW[tid]; bsh[tid] = bias[tid]; }
    __syncthreads();

    int n = blockIdx.x * 256 + tid;
    if (n >= NN) return;

    float xv[32];
    const float4* xp = (const float4*)(x + (size_t)n * 32);
#pragma unroll
    for (int j = 0; j < 8; j++) {
        float4 t = xp[j];
        xv[4*j] = t.x; xv[4*j+1] = t.y; xv[4*j+2] = t.z; xv[4*j+3] = t.w;
    }
    u64 acc[16];
#pragma unroll
    for (int m = 0; m < 16; m++) acc[m] = pack2(0.f, 0.f);
#pragma unroll
    for (int f = 0; f < 32; f++) {
        u64 xf = pack2(xv[f], xv[f]);
        const ulonglong2* rp = (const ulonglong2*)(Rs + f * 32);
#pragma unroll
        for (int j = 0; j < 8; j++) {
            ulonglong2 w = rp[j];
            acc[2*j]   = fma2(xf, w.x, acc[2*j]);
            acc[2*j+1] = fma2(xf, w.y, acc[2*j+1]);
        }
    }
    float xr[32];
#pragma unroll
    for (int m = 0; m < 16; m++) unpack2(acc[m], xr[2*m], xr[2*m+1]);

    float rd = 0.f;
#pragma unroll
    for (int o = 0; o < 32; o++) rd += xr[o] * a1s[o];
    g_rdot[n]  = rd;
    g_denom[n] = 0.f;

    float4* xrbp = (float4*)(g_xrb + (size_t)n * 32);
    float4* accp = (float4*)(g_acc + (size_t)n * 32);
#pragma unroll
    for (int j = 0; j < 8; j++) {
        float4 v;
        v.x = xr[4*j]   + bsh[4*j];
        v.y = xr[4*j+1] + bsh[4*j+1];
        v.z = xr[4*j+2] + bsh[4*j+2];
        v.w = xr[4*j+3] + bsh[4*j+3];
        xrbp[j] = v;
        accp[j] = make_float4(0.f, 0.f, 0.f, 0.f);
    }
}

// ---------------------------------------------------------------------------
// K2: xw[n,k,:] = fp16( x[n,:] @ W[k] )   (FFMA2 compute, fp16 store)
// ---------------------------------------------------------------------------
__global__ __launch_bounds__(256) void k2_xw(
    const float* __restrict__ x, const float* __restrict__ W)
{
    __shared__ __align__(16) float Ws[1024];
    int tid = threadIdx.x;
    int n = blockIdx.x * 256 + tid;
    bool act = (n < NN);

    float xv[32];
    if (act) {
        const float4* xp = (const float4*)(x + (size_t)n * 32);
#pragma unroll
        for (int j = 0; j < 8; j++) {
            float4 t = xp[j];
            xv[4*j] = t.x; xv[4*j+1] = t.y; xv[4*j+2] = t.z; xv[4*j+3] = t.w;
        }
    }
    uint4* outp = g_xwh + (size_t)n * 100;

#pragma unroll 1
    for (int k = 0; k < 25; k++) {
        __syncthreads();
        ((float4*)Ws)[tid] = ((const float4*)(W + k * 1024))[tid];
        __syncthreads();
        if (act) {
            u64 acc[16];
#pragma unroll
            for (int m = 0; m < 16; m++) acc[m] = pack2(0.f, 0.f);
#pragma unroll
            for (int f = 0; f < 32; f++) {
                u64 xf = pack2(xv[f], xv[f]);
                const ulonglong2* rp = (const ulonglong2*)(Ws + f * 32);
#pragma unroll
                for (int j = 0; j < 8; j++) {
                    ulonglong2 w = rp[j];
                    acc[2*j]   = fma2(xf, w.x, acc[2*j]);
                    acc[2*j+1] = fma2(xf, w.y, acc[2*j+1]);
                }
            }
            // convert 32 fp32 -> 16 half2 -> 4 uint4 (64B row)
#pragma unroll
            for (int j = 0; j < 4; j++) {
                uint4 v;
                v.x = h2bits(acc[4*j]);
                v.y = h2bits(acc[4*j+1]);
                v.z = h2bits(acc[4*j+2]);
                v.w = h2bits(acc[4*j+3]);
                outp[k * 4 + j] = v;
            }
        }
    }
}

// ---------------------------------------------------------------------------
// K3: single edge pass, 4 lanes/edge (8 feats = 16B of fp16 per lane per tap)
// ---------------------------------------------------------------------------
__global__ __launch_bounds__(256) void k3_edge(
    const int* __restrict__ ei, const float* __restrict__ pseudo,
    const float* __restrict__ attW)
{
    int t = blockIdx.x * 256 + threadIdx.x;
    int e   = t >> 2;
    int sub = t & 3;

    int row = __ldg(ei + e);
    int col = __ldg(ei + NE + e);
    float p0 = __ldg(pseudo + 2 * e)     * 4.f;
    float p1 = __ldg(pseudo + 2 * e + 1) * 4.f;
    float fl0 = floorf(p0), fl1 = floorf(p1);
    float fr0 = p0 - fl0,   fr1 = p1 - fl1;
    int i0 = (int)fl0, i1 = (int)fl1;

    const uint4* base = g_xwh + (size_t)col * 100 + sub;
    float m0=0.f,m1=0.f,m2=0.f,m3=0.f,m4=0.f,m5=0.f,m6=0.f,m7=0.f;
#pragma unroll
    for (int s = 0; s < 4; s++) {
        int o0 = s & 1, o1 = (s >> 1) & 1;
        float b = (o0 ? fr0 : 1.f - fr0) * (o1 ? fr1 : 1.f - fr1);
        int w = min(i0 + o0, 4) + 5 * min(i1 + o1, 4);
        uint4 v = __ldg(base + w * 4);
        float2 f0 = __half22float2(*reinterpret_cast<const __half2*>(&v.x));
        float2 f1 = __half22float2(*reinterpret_cast<const __half2*>(&v.y));
        float2 f2 = __half22float2(*reinterpret_cast<const __half2*>(&v.z));
        float2 f3 = __half22float2(*reinterpret_cast<const __half2*>(&v.w));
        m0 = fmaf(b, f0.x, m0); m1 = fmaf(b, f0.y, m1);
        m2 = fmaf(b, f1.x, m2); m3 = fmaf(b, f1.y, m3);
        m4 = fmaf(b, f2.x, m4); m5 = fmaf(b, f2.y, m5);
        m6 = fmaf(b, f3.x, m6); m7 = fmaf(b, f3.y, m7);
    }

    const float4* a2p = ((const float4*)(attW + 32)) + 2 * sub;
    float4 a0 = __ldg(a2p), a1 = __ldg(a2p + 1);
    float d = m0*a0.x + m1*a0.y + m2*a0.z + m3*a0.w
            + m4*a1.x + m5*a1.y + m6*a1.z + m7*a1.w;
    d += __shfl_xor_sync(0xffffffffu, d, 1);
    d += __shfl_xor_sync(0xffffffffu, d, 2);

    float alpha = d + __ldg(g_rdot + row);
    alpha = (alpha > 0.f) ? alpha : 0.2f * alpha;
    float ex = __expf(alpha);            // softmax max-shift cancels in the ratio

    if (sub == 0) atomicAdd(g_denom + row, ex);

    float* ap = g_acc + (size_t)row * 32 + sub * 8;
    asm volatile("red.global.add.v4.f32 [%0], {%1,%2,%3,%4};"
                 :: "l"(ap), "f"(m0 * ex), "f"(m1 * ex),
                    "f"(m2 * ex), "f"(m3 * ex) : "memory");
    asm volatile("red.global.add.v4.f32 [%0], {%1,%2,%3,%4};"
                 :: "l"(ap + 4), "f"(m4 * ex), "f"(m5 * ex),
                    "f"(m6 * ex), "f"(m7 * ex) : "memory");
}

// ---------------------------------------------------------------------------
// K4: out = acc / (denom + 1e-16) + (x_root + bias)
// ---------------------------------------------------------------------------
__global__ __launch_bounds__(256) void k4_out(float* __restrict__ out)
{
    int i = blockIdx.x * 256 + threadIdx.x;
    int n = i >> 3;
    float r = 1.f / (g_denom[n] + 1e-16f);
    float4 a  = ((const float4*)g_acc)[i];
    float4 xr = ((const float4*)g_xrb)[i];
    float4 o;
    o.x = fmaf(a.x, r, xr.x);
    o.y = fmaf(a.y, r, xr.y);
    o.z = fmaf(a.z, r, xr.z);
    o.w = fmaf(a.w, r, xr.w);
    ((float4*)out)[i] = o;
}

extern "C" void kernel_launch(void* const* d_in, const int* in_sizes, int n_in,
                              void* d_out, int out_size)
{
    const float* x      = (const float*)d_in[0];
    const int*   ei     = (const int*)d_in[1];
    const float* pseudo = (const float*)d_in[2];
    const float* W      = (const float*)d_in[3];
    const float* rootW  = (const float*)d_in[4];
    const float* attW   = (const float*)d_in[5];
    const float* bias   = (const float*)d_in[6];
    float* out = (float*)d_out;

    k1_node<<<(NN + 255) / 256, 256>>>(x, rootW, attW, bias);
    k2_xw  <<<(NN + 255) / 256, 256>>>(x, W);
    k3_edge<<<(NE * 4) / 256, 256>>>(ei, pseudo, attW);
    k4_out <<<(NN * 32 / 4) / 256, 256>>>(out);
}

// round 3
// speedup vs baseline: 1.7589x; 1.7589x over previous
#include <cuda_runtime.h>
#include <cuda_fp16.h>

#define NN 100000
#define NE 1600000

// xw in fp16: [N][25 kernels][32 feats] = 1600B/node = 160 MB scratch
__device__ uint2 g_xwh[(size_t)NN * 200];      // 200 uint2 (1600B) per node
__device__ float g_acc[(size_t)NN * 32];
__device__ float g_xrb[(size_t)NN * 32];
__device__ float g_rdot[NN];
__device__ float g_denom[NN];

typedef unsigned long long u64;

__device__ __forceinline__ u64 pack2(float a, float b) {
    u64 r; asm("mov.b64 %0,{%1,%2};" : "=l"(r) : "f"(a), "f"(b)); return r;
}
__device__ __forceinline__ void unpack2(u64 v, float& a, float& b) {
    asm("mov.b64 {%0,%1},%2;" : "=f"(a), "=f"(b) : "l"(v));
}
// packed fp32x2 FMA — 2x scalar FFMA throughput on sm_103a
__device__ __forceinline__ u64 fma2(u64 a, u64 b, u64 c) {
    u64 d; asm("fma.rn.f32x2 %0,%1,%2,%3;" : "=l"(d) : "l"(a), "l"(b), "l"(c)); return d;
}
// fp32 pair -> packed half2 bits
__device__ __forceinline__ unsigned h2bits(u64 v) {
    float a, b; unpack2(v, a, b);
    unsigned r; asm("cvt.rn.f16x2.f32 %0,%2,%1;" : "=r"(r) : "f"(a), "f"(b));
    return r;   // low half = a, high half = b
}

// ---------------------------------------------------------------------------
// K1: per-node root transform + attention dot + zero-init of accumulators
// ---------------------------------------------------------------------------
__global__ __launch_bounds__(256) void k1_node(
    const float* __restrict__ x, const float* __restrict__ rootW,
    const float* __restrict__ attW, const float* __restrict__ bias)
{
    __shared__ __align__(16) float Rs[1024];
    __shared__ float a1s[32], bsh[32];
    int tid = threadIdx.x;
    ((float4*)Rs)[tid] = ((const float4*)rootW)[tid];
    if (tid < 32) { a1s[tid] = attW[tid]; bsh[tid] = bias[tid]; }
    __syncthreads();

    int n = blockIdx.x * 256 + tid;
    if (n >= NN) return;

    float xv[32];
    const float4* xp = (const float4*)(x + (size_t)n * 32);
#pragma unroll
    for (int j = 0; j < 8; j++) {
        float4 t = xp[j];
        xv[4*j] = t.x; xv[4*j+1] = t.y; xv[4*j+2] = t.z; xv[4*j+3] = t.w;
    }
    u64 acc[16];
#pragma unroll
    for (int m = 0; m < 16; m++) acc[m] = pack2(0.f, 0.f);
#pragma unroll
    for (int f = 0; f < 32; f++) {
        u64 xf = pack2(xv[f], xv[f]);
        const ulonglong2* rp = (const ulonglong2*)(Rs + f * 32);
#pragma unroll
        for (int j = 0; j < 8; j++) {
            ulonglong2 w = rp[j];
            acc[2*j]   = fma2(xf, w.x, acc[2*j]);
            acc[2*j+1] = fma2(xf, w.y, acc[2*j+1]);
        }
    }
    float xr[32];
#pragma unroll
    for (int m = 0; m < 16; m++) unpack2(acc[m], xr[2*m], xr[2*m+1]);

    float rd = 0.f;
#pragma unroll
    for (int o = 0; o < 32; o++) rd += xr[o] * a1s[o];
    g_rdot[n]  = rd;
    g_denom[n] = 0.f;

    float4* xrbp = (float4*)(g_xrb + (size_t)n * 32);
    float4* accp = (float4*)(g_acc + (size_t)n * 32);
#pragma unroll
    for (int j = 0; j < 8; j++) {
        float4 v;
        v.x = xr[4*j]   + bsh[4*j];
        v.y = xr[4*j+1] + bsh[4*j+1];
        v.z = xr[4*j+2] + bsh[4*j+2];
        v.w = xr[4*j+3] + bsh[4*j+3];
        xrbp[j] = v;
        accp[j] = make_float4(0.f, 0.f, 0.f, 0.f);
    }
}

// ---------------------------------------------------------------------------
// K2: xw[n,k,:] = fp16( x[n,:] @ W[k] )   (FFMA2 compute, fp16 store)
// ---------------------------------------------------------------------------
__global__ __launch_bounds__(256) void k2_xw(
    const float* __restrict__ x, const float* __restrict__ W)
{
    __shared__ __align__(16) float Ws[1024];
    int tid = threadIdx.x;
    int n = blockIdx.x * 256 + tid;
    bool act = (n < NN);

    float xv[32];
    if (act) {
        const float4* xp = (const float4*)(x + (size_t)n * 32);
#pragma unroll
        for (int j = 0; j < 8; j++) {
            float4 t = xp[j];
            xv[4*j] = t.x; xv[4*j+1] = t.y; xv[4*j+2] = t.z; xv[4*j+3] = t.w;
        }
    }
    uint4* outp = ((uint4*)g_xwh) + (size_t)n * 100;

#pragma unroll 1
    for (int k = 0; k < 25; k++) {
        __syncthreads();
        ((float4*)Ws)[tid] = ((const float4*)(W + k * 1024))[tid];
        __syncthreads();
        if (act) {
            u64 acc[16];
#pragma unroll
            for (int m = 0; m < 16; m++) acc[m] = pack2(0.f, 0.f);
#pragma unroll
            for (int f = 0; f < 32; f++) {
                u64 xf = pack2(xv[f], xv[f]);
                const ulonglong2* rp = (const ulonglong2*)(Ws + f * 32);
#pragma unroll
                for (int j = 0; j < 8; j++) {
                    ulonglong2 w = rp[j];
                    acc[2*j]   = fma2(xf, w.x, acc[2*j]);
                    acc[2*j+1] = fma2(xf, w.y, acc[2*j+1]);
                }
            }
#pragma unroll
            for (int j = 0; j < 4; j++) {
                uint4 v;
                v.x = h2bits(acc[4*j]);
                v.y = h2bits(acc[4*j+1]);
                v.z = h2bits(acc[4*j+2]);
                v.w = h2bits(acc[4*j+3]);
                outp[k * 4 + j] = v;
            }
        }
    }
}

// ---------------------------------------------------------------------------
// K3: single edge pass, 8 lanes/edge (round-1 warp shape), fp16 gather.
//   Each lane loads 8B (4 feats) per tap; 4 distinct rows per warp-LDG.
// ---------------------------------------------------------------------------
__global__ __launch_bounds__(256) void k3_edge(
    const int* __restrict__ ei, const float* __restrict__ pseudo,
    const float* __restrict__ attW)
{
    int t = blockIdx.x * 256 + threadIdx.x;
    int e   = t >> 3;
    int sub = t & 7;

    int row = __ldg(ei + e);
    int col = __ldg(ei + NE + e);
    float p0 = __ldg(pseudo + 2 * e)     * 4.f;   // (K-1) = 4
    float p1 = __ldg(pseudo + 2 * e + 1) * 4.f;
    float fl0 = floorf(p0), fl1 = floorf(p1);
    float fr0 = p0 - fl0,   fr1 = p1 - fl1;
    int i0 = (int)fl0, i1 = (int)fl1;

    const uint2* base = g_xwh + (size_t)col * 200 + sub;
    float m0 = 0.f, m1 = 0.f, m2 = 0.f, m3 = 0.f;
#pragma unroll
    for (int s = 0; s < 4; s++) {
        int o0 = s & 1, o1 = (s >> 1) & 1;
        float b = (o0 ? fr0 : 1.f - fr0) * (o1 ? fr1 : 1.f - fr1);
        int w = min(i0 + o0, 4) + 5 * min(i1 + o1, 4);
        uint2 v = __ldg(base + w * 8);
        float2 f0 = __half22float2(*reinterpret_cast<const __half2*>(&v.x));
        float2 f1 = __half22float2(*reinterpret_cast<const __half2*>(&v.y));
        m0 = fmaf(b, f0.x, m0); m1 = fmaf(b, f0.y, m1);
        m2 = fmaf(b, f1.x, m2); m3 = fmaf(b, f1.y, m3);
    }

    float4 a2 = __ldg(((const float4*)(attW + 32)) + sub);
    float d = m0 * a2.x + m1 * a2.y + m2 * a2.z + m3 * a2.w;
    d += __shfl_xor_sync(0xffffffffu, d, 1);
    d += __shfl_xor_sync(0xffffffffu, d, 2);
    d += __shfl_xor_sync(0xffffffffu, d, 4);

    float alpha = d + __ldg(g_rdot + row);
    alpha = (alpha > 0.f) ? alpha : 0.2f * alpha;         // leaky relu
    float ex = __expf(alpha);             // softmax max-shift cancels in ratio

    if (sub == 0) atomicAdd(g_denom + row, ex);

    float* ap = g_acc + (size_t)row * 32 + sub * 4;
    asm volatile("red.global.add.v4.f32 [%0], {%1,%2,%3,%4};"
                 :: "l"(ap), "f"(m0 * ex), "f"(m1 * ex),
                    "f"(m2 * ex), "f"(m3 * ex)
                 : "memory");
}

// ---------------------------------------------------------------------------
// K4: out = acc / (denom + 1e-16) + (x_root + bias)
// ---------------------------------------------------------------------------
__global__ __launch_bounds__(256) void k4_out(float* __restrict__ out)
{
    int i = blockIdx.x * 256 + threadIdx.x;
    int n = i >> 3;
    float r = 1.f / (g_denom[n] + 1e-16f);
    float4 a  = ((const float4*)g_acc)[i];
    float4 xr = ((const float4*)g_xrb)[i];
    float4 o;
    o.x = fmaf(a.x, r, xr.x);
    o.y = fmaf(a.y, r, xr.y);
    o.z = fmaf(a.z, r, xr.z);
    o.w = fmaf(a.w, r, xr.w);
    ((float4*)out)[i] = o;
}

extern "C" void kernel_launch(void* const* d_in, const int* in_sizes, int n_in,
                              void* d_out, int out_size)
{
    const float* x      = (const float*)d_in[0];
    const int*   ei     = (const int*)d_in[1];
    const float* pseudo = (const float*)d_in[2];
    const float* W      = (const float*)d_in[3];
    const float* rootW  = (const float*)d_in[4];
    const float* attW   = (const float*)d_in[5];
    const float* bias   = (const float*)d_in[6];
    float* out = (float*)d_out;

    k1_node<<<(NN + 255) / 256, 256>>>(x, rootW, attW, bias);
    k2_xw  <<<(NN + 255) / 256, 256>>>(x, W);
    k3_edge<<<(NE * 8) / 256, 256>>>(ei, pseudo, attW);
    k4_out <<<(NN * 32 / 4) / 256, 256>>>(out);
}